// round 7
// baseline (speedup 1.0000x reference)
#include <cuda_runtime.h>

#define Bn 4
#define Cn 256
#define Hn 128
#define Wn 128
#define N_ROIS 512
#define Pn 7
#define SCALE_F 0.0625f
#define GAMMA_F 0.1f

// NHWC scratch: [B, H, W, C] = 16,777,216 floats (64 MB)
__device__ float g_xt[Bn * Hn * Wn * Cn];

// ---------------------------------------------------------------------------
// NCHW -> NHWC transpose. 256 threads handle 128 channels x 32 width at fixed
// (b,y). All 4 LDG.128 batched up front (MLP=4), ONE barrier, then 4 coalesced
// STG.128 per thread (each warp writes 512B contiguous).
// ---------------------------------------------------------------------------
__global__ void __launch_bounds__(256) transpose_nchw_nhwc(const float* __restrict__ x) {
    __shared__ float tile[4][32][33];
    const int bhy = blockIdx.z;          // b*H + y
    const int b = bhy >> 7;
    const int y = bhy & 127;
    const int w0 = blockIdx.x * 32;
    const int c0 = blockIdx.y * 128;
    const int tid = threadIdx.x;

    // load mapping: cl = channel row within 32, w4 = w quad
    const int cl = tid >> 3;             // 0..31
    const int w4 = (tid & 7) * 4;        // 0,4,..28

    float4 v[4];
#pragma unroll
    for (int ct = 0; ct < 4; ct++)
        v[ct] = *(const float4*)(x + (((size_t)(b * Cn + c0 + ct * 32 + cl) * Hn + y) * Wn + w0 + w4));
#pragma unroll
    for (int ct = 0; ct < 4; ct++) {
        tile[ct][cl][w4 + 0] = v[ct].x;
        tile[ct][cl][w4 + 1] = v[ct].y;
        tile[ct][cl][w4 + 2] = v[ct].z;
        tile[ct][cl][w4 + 3] = v[ct].w;
    }
    __syncthreads();

    // store mapping: q = channel quad 0..31 (128 channels), ws = w row base
    const int q  = tid & 31;             // channel quad within 128 channels
    const int ws = tid >> 5;             // 0..7
    const int ct = q >> 3;
    const int cq = (q & 7) * 4;
#pragma unroll
    for (int j = 0; j < 4; j++) {
        const int wr = ws + j * 8;       // 0..31
        float4 o;
        o.x = tile[ct][cq + 0][wr];
        o.y = tile[ct][cq + 1][wr];
        o.z = tile[ct][cq + 2][wr];
        o.w = tile[ct][cq + 3][wr];
        *(float4*)(g_xt + ((size_t)(bhy * Wn + w0 + wr) * Cn + c0 + q * 4)) = o;
    }
}

// ---------------------------------------------------------------------------
// Deformable ROI pool (R5 dense version — proven fastest). One block per ROI,
// 512 threads = (bin-slice bs = tid>>6, 0..7) x (channel-quad c4 = tid&63).
// smem ~54.4KB x 2 CTAs/SM -> ~119KB L1D carveout + 32 warps/SM.
// 2-bin unroll keeps two independent 16-load gather chains in flight.
// ---------------------------------------------------------------------------
#define SOUT_PITCH 260   // 16B-aligned rows

__device__ __forceinline__ void gather_bin(
    const float* __restrict__ base,
    const float* __restrict__ s_w,
    const int*   __restrict__ s_off,
    int bin, float4& acc)
{
    const float4* wv = (const float4*)(s_w + bin * 16);
    const int4 ro = ((const int4*)(s_off + bin * 8))[0];
    const int4 co = ((const int4*)(s_off + bin * 8))[1];
    const int rr[4] = {ro.x, ro.y, ro.z, ro.w};
    const int cc[4] = {co.x, co.y, co.z, co.w};
    float ax = 0.f, ay = 0.f, az = 0.f, aw = 0.f;
#pragma unroll
    for (int r = 0; r < 4; r++) {
        const float4 w = wv[r];
        float4 v0 = *(const float4*)(base + rr[r] + cc[0]);
        float4 v1 = *(const float4*)(base + rr[r] + cc[1]);
        float4 v2 = *(const float4*)(base + rr[r] + cc[2]);
        float4 v3 = *(const float4*)(base + rr[r] + cc[3]);
        ax = fmaf(w.x, v0.x, ax); ay = fmaf(w.x, v0.y, ay);
        az = fmaf(w.x, v0.z, az); aw = fmaf(w.x, v0.w, aw);
        ax = fmaf(w.y, v1.x, ax); ay = fmaf(w.y, v1.y, ay);
        az = fmaf(w.y, v1.z, az); aw = fmaf(w.y, v1.w, aw);
        ax = fmaf(w.z, v2.x, ax); ay = fmaf(w.z, v2.y, ay);
        az = fmaf(w.z, v2.z, az); aw = fmaf(w.z, v2.w, aw);
        ax = fmaf(w.w, v3.x, ax); ay = fmaf(w.w, v3.y, ay);
        az = fmaf(w.w, v3.z, az); aw = fmaf(w.w, v3.w, aw);
    }
    acc = make_float4(ax, ay, az, aw);
}

__global__ void __launch_bounds__(512, 2) dcn_pool_kernel(
    const float* __restrict__ rois,
    const float* __restrict__ offset,
    float* __restrict__ out)
{
    extern __shared__ float smem[];
    float* s_out = smem;                           // 49*260 = 12740
    float* s_w   = smem + 49 * SOUT_PITCH;         // 49*16  = 784
    int*   s_off = (int*)(s_w + 49 * 16);          // 49*8   = 392

    const int n = blockIdx.x;
    const int tid = threadIdx.x;

    const int bidx = (int)rois[n * 5 + 0];

    if (tid < 49) {
        const float x1 = rois[n * 5 + 1] * SCALE_F - 0.5f;
        const float y1 = rois[n * 5 + 2] * SCALE_F - 0.5f;
        const float x2 = rois[n * 5 + 3] * SCALE_F - 0.5f;
        const float y2 = rois[n * 5 + 4] * SCALE_F - 0.5f;
        const float rw = fmaxf(x2 - x1, 1.0f);
        const float rh = fmaxf(y2 - y1, 1.0f);
        const float bw = rw * (1.0f / Pn);
        const float bh = rh * (1.0f / Pn);

        const int ph = tid / 7;
        const int pw = tid - ph * 7;
        const float ox = offset[n * 98 + tid];
        const float oy = offset[n * 98 + 49 + tid];
        const float ybase = y1 + (float)ph * bh + GAMMA_F * rh * oy;
        const float xbase = x1 + (float)pw * bw + GAMMA_F * rw * ox;

        // ---- y direction: 4 samples -> weights over 4 contiguous rows ----
        float wy[4] = {0.f, 0.f, 0.f, 0.f};
        int   y0a[4];
        float lya[4], va[4];
        int rmin = Hn;
#pragma unroll
        for (int i = 0; i < 4; i++) {
            const float s  = ((float)i + 0.5f) * 0.25f;
            const float ys = ybase + s * bh;
            const float v  = (ys > -1.0f && ys < (float)Hn) ? 0.25f : 0.0f;
            const float yc = fminf(fmaxf(ys, 0.0f), (float)(Hn - 1));
            const int   y0 = (int)yc;
            y0a[i] = y0; lya[i] = yc - (float)y0; va[i] = v;
            rmin = min(rmin, y0);
        }
#pragma unroll
        for (int i = 0; i < 4; i++) {
            const int sl0 = min(y0a[i] - rmin, 3);
            const int sl1 = min(min(y0a[i] + 1, Hn - 1) - rmin, 3);
            wy[sl0] += (1.0f - lya[i]) * va[i];
            wy[sl1] += lya[i] * va[i];
        }

        // ---- x direction ----
        float wx[4] = {0.f, 0.f, 0.f, 0.f};
        int   x0a[4];
        float lxa[4], vxa[4];
        int cmin = Wn;
#pragma unroll
        for (int j = 0; j < 4; j++) {
            const float s  = ((float)j + 0.5f) * 0.25f;
            const float xs = xbase + s * bw;
            const float v  = (xs > -1.0f && xs < (float)Wn) ? 0.25f : 0.0f;
            const float xc = fminf(fmaxf(xs, 0.0f), (float)(Wn - 1));
            const int   x0 = (int)xc;
            x0a[j] = x0; lxa[j] = xc - (float)x0; vxa[j] = v;
            cmin = min(cmin, x0);
        }
#pragma unroll
        for (int j = 0; j < 4; j++) {
            const int sl0 = min(x0a[j] - cmin, 3);
            const int sl1 = min(min(x0a[j] + 1, Wn - 1) - cmin, 3);
            wx[sl0] += (1.0f - lxa[j]) * vxa[j];
            wx[sl1] += lxa[j] * vxa[j];
        }

        // ---- weights (16) + row/col offsets (4+4) ----
#pragma unroll
        for (int r = 0; r < 4; r++)
#pragma unroll
            for (int q = 0; q < 4; q++)
                s_w[tid * 16 + r * 4 + q] = wy[r] * wx[q];
#pragma unroll
        for (int k = 0; k < 4; k++) {
            s_off[tid * 8 + k]     = min(rmin + k, Hn - 1) * (Wn * Cn);
            s_off[tid * 8 + 4 + k] = min(cmin + k, Wn - 1) * Cn;
        }
    }
    __syncthreads();

    // ---- gather: thread = (bin slice bs 0..7) x (channel quad c4 0..63) ----
    const int c4 = tid & 63;
    const int bs = tid >> 6;
    const float* base = g_xt + (size_t)(bidx * Hn * Wn) * Cn + c4 * 4;
    float* sout_row = s_out + c4 * 4;

    // 2-bin unrolled: pairs (bin, bin+8), stride 16
    int bin = bs;
    for (; bin + 8 < 49; bin += 16) {
        float4 accA, accB;
        gather_bin(base, s_w, s_off, bin,     accA);
        gather_bin(base, s_w, s_off, bin + 8, accB);
        *(float4*)(sout_row + bin       * SOUT_PITCH) = accA;
        *(float4*)(sout_row + (bin + 8) * SOUT_PITCH) = accB;
    }
    if (bin < 49) {
        float4 accA;
        gather_bin(base, s_w, s_off, bin, accA);
        *(float4*)(sout_row + bin * SOUT_PITCH) = accA;
    }
    __syncthreads();

    // ---- coalesced store of the ROI's contiguous [C][49] output chunk ----
    float* o = out + (size_t)n * (Cn * 49);
    for (int l = tid; l < Cn * 49; l += 512) {
        const int c = l / 49;
        const int b = l - c * 49;
        o[l] = s_out[b * SOUT_PITCH + c];
    }
}

extern "C" void kernel_launch(void* const* d_in, const int* in_sizes, int n_in,
                              void* d_out, int out_size) {
    const float* x      = (const float*)d_in[0];
    const float* rois   = (const float*)d_in[1];
    const float* offset = (const float*)d_in[2];
    float* out = (float*)d_out;

    // NCHW -> NHWC
    dim3 tgrid(Wn / 32, Cn / 128, Bn * Hn);
    transpose_nchw_nhwc<<<tgrid, 256>>>(x);

    const int smem_bytes = (49 * SOUT_PITCH + 49 * 16) * sizeof(float) + 49 * 8 * sizeof(int);
    static bool attr_set = false;
    if (!attr_set) {
        cudaFuncSetAttribute(dcn_pool_kernel,
                             cudaFuncAttributeMaxDynamicSharedMemorySize, smem_bytes);
        attr_set = true;
    }
    dcn_pool_kernel<<<N_ROIS, 512, smem_bytes>>>(rois, offset, out);
}